// round 4
// baseline (speedup 1.0000x reference)
#include <cuda_runtime.h>
#include <cstdint>

// ---------------------------------------------------------------------------
// GAT, 3 layers. tcgen05 is unavailable (harness PTX target = compute_100,
// no 'a' suffix), so GEMM is SIMT fp32 with PACKED f32x2 FMA (2x FFMA rate).
// CSR built once; AGG = warp-per-node softmax aggregation, 8-edge batched.
// Softmax max-shift dropped (exact by shift invariance).
// ---------------------------------------------------------------------------

#define NNODES_MAX 50000
#define NEDGES_MAX 800000

__device__ float g_feat[NNODES_MAX * 128];
__device__ float g_h   [NNODES_MAX * 128];
__device__ float g_el  [NNODES_MAX * 4];
__device__ float g_er  [NNODES_MAX * 4];
__device__ int   g_cnt [NNODES_MAX];
__device__ int   g_row [NNODES_MAX + 1];
__device__ int   g_bsum[64];
__device__ int   g_srcperm[NEDGES_MAX];

// ------------------------------ CSR build ---------------------------------

__global__ void k_zero_int(int* p, int n) {
    int i = blockIdx.x * blockDim.x + threadIdx.x;
    if (i < n) p[i] = 0;
}

__global__ void k_count(const int* __restrict__ dst, int* __restrict__ cnt, int E) {
    int i = blockIdx.x * blockDim.x + threadIdx.x;
    if (i < E) atomicAdd(&cnt[dst[i]], 1);
}

__global__ void k_scan1(const int* __restrict__ cnt, int* __restrict__ row,
                        int* __restrict__ bsum, int N) {
    __shared__ int sh[1024];
    int tid = threadIdx.x;
    int idx = blockIdx.x * 1024 + tid;
    int c = (idx < N) ? cnt[idx] : 0;
    sh[tid] = c;
    __syncthreads();
    #pragma unroll
    for (int off = 1; off < 1024; off <<= 1) {
        int t = (tid >= off) ? sh[tid - off] : 0;
        __syncthreads();
        sh[tid] += t;
        __syncthreads();
    }
    if (idx < N) row[idx] = sh[tid] - c;
    if (tid == 1023) bsum[blockIdx.x] = sh[1023];
}

__global__ void k_scan2(int* __restrict__ bsum, int nb) {
    __shared__ int sh[64];
    int tid = threadIdx.x;
    int v = (tid < nb) ? bsum[tid] : 0;
    sh[tid] = v;
    __syncthreads();
    #pragma unroll
    for (int off = 1; off < 64; off <<= 1) {
        int t = (tid >= off) ? sh[tid - off] : 0;
        __syncthreads();
        sh[tid] += t;
        __syncthreads();
    }
    if (tid < nb) bsum[tid] = sh[tid] - v;
}

__global__ void k_scan3(int* __restrict__ row, const int* __restrict__ bsum,
                        int* __restrict__ cursor, int N, int E) {
    int idx = blockIdx.x * 1024 + threadIdx.x;
    if (idx < N) {
        int v = row[idx] + bsum[blockIdx.x];
        row[idx] = v;
        cursor[idx] = v;
    }
    if (idx == 0) row[N] = E;
}

__global__ void k_scatter(const int* __restrict__ src, const int* __restrict__ dst,
                          int* __restrict__ cursor, int* __restrict__ srcperm, int E) {
    int i = blockIdx.x * blockDim.x + threadIdx.x;
    if (i < E) {
        int d = dst[i];
        int pos = atomicAdd(&cursor[d], 1);
        srcperm[pos] = src[i];
    }
}

// ------------------------------ GEMM ---------------------------------------
// out[N,C] = X[N,128] @ W[128,C].
// Block: 128 rows x C cols, THREADS = 2*C. Thread: 8 rows x 8 cols, with the
// 8 columns held as 4 packed f32x2 accumulators -> fma.rn.f32x2 (2x FFMA).
// W SMEM-resident k-major [128][C]; X chunk transposed to k-major [32][128]
// with XOR swizzle (conflict-free STS/LDS).

template <int C>
__global__ void __launch_bounds__(2 * C, 2)
k_gemm(const float* __restrict__ X, const float* __restrict__ W,
       float* __restrict__ out, int N) {
    extern __shared__ float sh[];
    float* Ws = sh;             // 128 * C
    float* Xs = sh + 128 * C;   // 32 * 128 (k-major, swizzled)

    constexpr int THREADS = 2 * C;
    const int tid = threadIdx.x;
    const int r0 = blockIdx.x * 128;

    constexpr int CT = C / 8;          // threads per row-group in col dim
    const int ci = tid % CT;
    const int ri = tid / CT;           // 0..15

    // load full W (k-major [128][C])
    #pragma unroll
    for (int i = tid; i < 128 * C / 4; i += THREADS)
        ((float4*)Ws)[i] = ((const float4*)W)[i];

    unsigned long long acc2[8][4];
    #pragma unroll
    for (int i = 0; i < 8; ++i)
        #pragma unroll
        for (int j = 0; j < 4; ++j) acc2[i][j] = 0ull;

    #pragma unroll 1
    for (int kc = 0; kc < 4; ++kc) {
        // load & transpose X chunk: 128 rows x 32 k
        #pragma unroll
        for (int i = tid; i < 1024; i += THREADS) {
            int row = i >> 3;
            int k4  = i & 7;
            int grow = r0 + row;
            float4 v = (grow < N)
                ? ((const float4*)X)[(size_t)grow * 32 + kc * 8 + k4]
                : make_float4(0.f, 0.f, 0.f, 0.f);
            int pr = row ^ (k4 << 2);
            Xs[(4 * k4 + 0) * 128 + pr] = v.x;
            Xs[(4 * k4 + 1) * 128 + pr] = v.y;
            Xs[(4 * k4 + 2) * 128 + pr] = v.z;
            Xs[(4 * k4 + 3) * 128 + pr] = v.w;
        }
        __syncthreads();

        #pragma unroll 2
        for (int k = 0; k < 32; ++k) {
            int swz = ((k >> 2) & 7) << 2;
            float4 a0 = *(const float4*)&Xs[k * 128 + ((ri * 8)     ^ swz)];
            float4 a1 = *(const float4*)&Xs[k * 128 + ((ri * 8 + 4) ^ swz)];
            int kk = kc * 32 + k;
            const ulonglong2* bp = (const ulonglong2*)&Ws[kk * C + ci * 8];
            ulonglong2 bA = bp[0];   // packed cols 0-1, 2-3
            ulonglong2 bB = bp[1];   // packed cols 4-5, 6-7
            unsigned long long bb[4] = {bA.x, bA.y, bB.x, bB.y};
            float a[8] = {a0.x, a0.y, a0.z, a0.w, a1.x, a1.y, a1.z, a1.w};
            #pragma unroll
            for (int i = 0; i < 8; ++i) {
                unsigned long long ad;
                asm("mov.b64 %0, {%1, %1};" : "=l"(ad) : "f"(a[i]));
                #pragma unroll
                for (int j = 0; j < 4; ++j)
                    asm("fma.rn.f32x2 %0, %1, %2, %0;"
                        : "+l"(acc2[i][j]) : "l"(ad), "l"(bb[j]));
            }
        }
        __syncthreads();
    }

    #pragma unroll
    for (int i = 0; i < 8; ++i) {
        int row = r0 + ri * 8 + i;
        if (row < N) {
            float r[8];
            #pragma unroll
            for (int j = 0; j < 4; ++j)
                asm("mov.b64 {%0, %1}, %2;"
                    : "=f"(r[2 * j]), "=f"(r[2 * j + 1]) : "l"(acc2[i][j]));
            float4* o = (float4*)(out + (size_t)row * C + ci * 8);
            o[0] = make_float4(r[0], r[1], r[2], r[3]);
            o[1] = make_float4(r[4], r[5], r[6], r[7]);
        }
    }
}

// ------------------------------ EL / ER ------------------------------------

template <int C, int H>
__global__ void k_elr(const float* __restrict__ feat, const float* __restrict__ al,
                      const float* __restrict__ ar, float* __restrict__ el,
                      float* __restrict__ er, int N) {
    int warp = (blockIdx.x * blockDim.x + threadIdx.x) >> 5;
    int lane = threadIdx.x & 31;
    if (warp >= N) return;
    constexpr int V = C / 32;
    constexpr int D = C / H;
    constexpr int G = D / V;

    float pl = 0.f, pr = 0.f;
    #pragma unroll
    for (int v = 0; v < V; ++v) {
        float f = feat[(size_t)warp * C + lane * V + v];
        pl += f * al[lane * V + v];
        pr += f * ar[lane * V + v];
    }
    #pragma unroll
    for (int off = G / 2; off > 0; off >>= 1) {
        pl += __shfl_xor_sync(0xffffffffu, pl, off);
        pr += __shfl_xor_sync(0xffffffffu, pr, off);
    }
    if ((lane % G) == 0) {
        int h = lane / G;
        el[warp * H + h] = pl;
        er[warp * H + h] = pr;
    }
}

// ------------------------------ Aggregation --------------------------------
// Warp per destination node; 8-edge batched loads for MLP.

template <int C, int H, bool RELU>
__global__ void k_agg(const float* __restrict__ feat, const float* __restrict__ el,
                      const float* __restrict__ er, const int* __restrict__ rowp,
                      const int* __restrict__ srcperm, const float* __restrict__ bias,
                      float* __restrict__ out, int N) {
    int warp = (blockIdx.x * blockDim.x + threadIdx.x) >> 5;
    int lane = threadIdx.x & 31;
    if (warp >= N) return;
    constexpr int V = C / 32;
    constexpr int D = C / H;
    const int h0 = (lane * V) / D;

    float erv = er[warp * H + h0];
    float acc[V];
    #pragma unroll
    for (int v = 0; v < V; ++v) acc[v] = 0.f;
    float denom = 0.f;

    int s = rowp[warp];
    const int send = rowp[warp + 1];

    #pragma unroll 1
    for (; s + 8 <= send; s += 8) {
        int a[8];
        #pragma unroll
        for (int q = 0; q < 8; ++q) a[q] = srcperm[s + q];
        float w[8];
        #pragma unroll
        for (int q = 0; q < 8; ++q) {
            float e = el[a[q] * H + h0] + erv;
            e = (e > 0.f) ? e : 0.2f * e;
            w[q] = __expf(e);
            denom += w[q];
        }
        if constexpr (V == 4) {
            #pragma unroll
            for (int q = 0; q < 8; ++q) {
                float4 f = ((const float4*)(feat + (size_t)a[q] * C))[lane];
                acc[0] += f.x * w[q]; acc[1] += f.y * w[q];
                acc[2] += f.z * w[q]; acc[3] += f.w * w[q];
            }
        } else {
            #pragma unroll
            for (int q = 0; q < 8; ++q) {
                float2 f = ((const float2*)(feat + (size_t)a[q] * C))[lane];
                acc[0] += f.x * w[q]; acc[1] += f.y * w[q];
            }
        }
    }
    for (; s < send; ++s) {
        int sn = srcperm[s];
        float e = el[sn * H + h0] + erv;
        e = (e > 0.f) ? e : 0.2f * e;
        float w = __expf(e);
        denom += w;
        if constexpr (V == 4) {
            float4 f = ((const float4*)(feat + (size_t)sn * C))[lane];
            acc[0] += f.x * w; acc[1] += f.y * w;
            acc[2] += f.z * w; acc[3] += f.w * w;
        } else {
            float2 f = ((const float2*)(feat + (size_t)sn * C))[lane];
            acc[0] += f.x * w; acc[1] += f.y * w;
        }
    }

    float inv = 1.f / fmaxf(denom, 1e-12f);
    float res[V];
    #pragma unroll
    for (int v = 0; v < V; ++v) {
        float o = acc[v] * inv + bias[lane * V + v];
        if (RELU) o = fmaxf(o, 0.f);
        res[v] = o;
    }
    if constexpr (V == 4) {
        ((float4*)(out + (size_t)warp * C))[lane] =
            make_float4(res[0], res[1], res[2], res[3]);
    } else {
        ((float2*)(out + (size_t)warp * C))[lane] = make_float2(res[0], res[1]);
    }
}

// ------------------------------ Host ---------------------------------------

extern "C" void kernel_launch(void* const* d_in, const int* in_sizes, int n_in,
                              void* d_out, int out_size) {
    const float* features = (const float*)d_in[0];
    const int*   src      = (const int*)d_in[1];
    const int*   dst      = (const int*)d_in[2];
    const float* W0  = (const float*)d_in[3];
    const float* al0 = (const float*)d_in[4];
    const float* ar0 = (const float*)d_in[5];
    const float* b0  = (const float*)d_in[6];
    const float* W1  = (const float*)d_in[7];
    const float* al1 = (const float*)d_in[8];
    const float* ar1 = (const float*)d_in[9];
    const float* b1  = (const float*)d_in[10];
    const float* W2  = (const float*)d_in[11];
    const float* al2 = (const float*)d_in[12];
    const float* ar2 = (const float*)d_in[13];
    const float* b2  = (const float*)d_in[14];

    const int N = in_sizes[0] / 128;
    const int E = in_sizes[1];

    float *feat, *h, *el, *er;
    int *cnt, *row, *bsum, *srcperm;
    cudaGetSymbolAddress((void**)&feat, g_feat);
    cudaGetSymbolAddress((void**)&h, g_h);
    cudaGetSymbolAddress((void**)&el, g_el);
    cudaGetSymbolAddress((void**)&er, g_er);
    cudaGetSymbolAddress((void**)&cnt, g_cnt);
    cudaGetSymbolAddress((void**)&row, g_row);
    cudaGetSymbolAddress((void**)&bsum, g_bsum);
    cudaGetSymbolAddress((void**)&srcperm, g_srcperm);

    const int smem128 = (128 * 128 + 32 * 128) * (int)sizeof(float); // 80 KB
    const int smem64  = (128 * 64  + 32 * 128) * (int)sizeof(float); // 48 KB
    cudaFuncSetAttribute(k_gemm<128>, cudaFuncAttributeMaxDynamicSharedMemorySize, smem128);
    cudaFuncSetAttribute(k_gemm<64>,  cudaFuncAttributeMaxDynamicSharedMemorySize, smem64);

    const int nb = (N + 1023) / 1024;
    const int gemm_blocks = (N + 127) / 128;
    const int node_warp_blocks = (N + 7) / 8;

    // CSR build, interleaved so launch #4 is k_gemm<128> (ncu capture target)
    k_zero_int<<<(N + 255) / 256, 256>>>(cnt, N);
    k_count<<<(E + 255) / 256, 256>>>(dst, cnt, E);
    k_scan1<<<nb, 1024>>>(cnt, row, bsum, N);

    // ---- Layer 0 GEMM (launch #4) ----
    k_gemm<128><<<gemm_blocks, 256, smem128>>>(features, W0, feat, N);

    k_scan2<<<1, 64>>>(bsum, nb);
    k_scan3<<<nb, 1024>>>(row, bsum, cnt, N, E);
    k_scatter<<<(E + 255) / 256, 256>>>(src, dst, cnt, srcperm, E);

    // ---- Layer 0 rest ----
    k_elr<128, 4><<<node_warp_blocks, 256>>>(feat, al0, ar0, el, er, N);
    k_agg<128, 4, true><<<node_warp_blocks, 256>>>(feat, el, er, row, srcperm, b0, h, N);

    // ---- Layer 1 ----
    k_gemm<128><<<gemm_blocks, 256, smem128>>>(h, W1, feat, N);
    k_elr<128, 4><<<node_warp_blocks, 256>>>(feat, al1, ar1, el, er, N);
    k_agg<128, 4, true><<<node_warp_blocks, 256>>>(feat, el, er, row, srcperm, b1, h, N);

    // ---- Layer 2 ----
    k_gemm<64><<<gemm_blocks, 128, smem64>>>(h, W2, feat, N);
    k_elr<64, 1><<<node_warp_blocks, 256>>>(feat, al2, ar2, el, er, N);
    k_agg<64, 1, false><<<node_warp_blocks, 256>>>(feat, el, er, row, srcperm, b2,
                                                   (float*)d_out, N);
}

// round 5
// speedup vs baseline: 1.2895x; 1.2895x over previous
#include <cuda_runtime.h>
#include <cuda_bf16.h>
#include <cstdint>

// ---------------------------------------------------------------------------
// GAT, 3 layers.
//   GEMM: Ampere-style warp MMA (mma.sync m16n8k16 bf16, fp32 acc) -- valid on
//         plain compute_100 PTX (tcgen05 is not). fp32 emulated by 3-term bf16
//         split: x*y ~= xh*yh + xl*yh + xh*yl  (~1e-5 rel err per layer).
//   CSR built once; AGG = warp-per-node softmax aggregation, 8-edge batched.
//   Softmax max-shift dropped (exact by shift invariance).
// ---------------------------------------------------------------------------

#define NNODES_MAX 50000
#define NEDGES_MAX 800000

__device__ float g_feat[NNODES_MAX * 128];
__device__ float g_h   [NNODES_MAX * 128];
__device__ float g_el  [NNODES_MAX * 4];
__device__ float g_er  [NNODES_MAX * 4];
__device__ int   g_cnt [NNODES_MAX];
__device__ int   g_row [NNODES_MAX + 1];
__device__ int   g_bsum[64];
__device__ int   g_srcperm[NEDGES_MAX];

// Pre-split, pre-swizzled W operands: [C n][128 k] bf16, row stride 256 B,
// 16B-chunk XOR swizzle. hi/lo per layer.
__device__ uint16_t g_whi0[128 * 128], g_wlo0[128 * 128];
__device__ uint16_t g_whi1[128 * 128], g_wlo1[128 * 128];
__device__ uint16_t g_whi2[64 * 128],  g_wlo2[64 * 128];

// ------------------------------ MMA helpers --------------------------------

#define LDSM4(r, addr)                                                        \
    asm volatile("ldmatrix.sync.aligned.m8n8.x4.shared.b16 {%0,%1,%2,%3}, [%4];" \
        : "=r"((r)[0]), "=r"((r)[1]), "=r"((r)[2]), "=r"((r)[3]) : "r"(addr))

#define MMA16816(d, a, b0, b1)                                                \
    asm volatile("mma.sync.aligned.m16n8k16.row.col.f32.bf16.bf16.f32 "       \
        "{%0,%1,%2,%3}, {%4,%5,%6,%7}, {%8,%9}, {%0,%1,%2,%3};"               \
        : "+f"((d)[0]), "+f"((d)[1]), "+f"((d)[2]), "+f"((d)[3])              \
        : "r"((a)[0]), "r"((a)[1]), "r"((a)[2]), "r"((a)[3]), "r"(b0), "r"(b1))

__device__ __forceinline__ uint32_t smem_u32(const void* p) {
    uint32_t a;
    asm("{ .reg .u64 t; cvta.to.shared.u64 t, %1; cvt.u32.u64 %0, t; }"
        : "=r"(a) : "l"(p));
    return a;
}

// split a float2 into packed bf16x2 hi and lo
__device__ __forceinline__ void split2(float2 v, uint32_t& hi, uint32_t& lo) {
    __nv_bfloat162 h2 = __float22bfloat162_rn(v);
    float rx = v.x - __bfloat162float(h2.x);
    float ry = v.y - __bfloat162float(h2.y);
    __nv_bfloat162 l2 = __float22bfloat162_rn(make_float2(rx, ry));
    hi = *(uint32_t*)&h2;
    lo = *(uint32_t*)&l2;
}

// swizzled byte offset within a [R rows][128 k] bf16 tile (row stride 256B)
__device__ __forceinline__ uint32_t tile_off(int r, int k) {
    return (uint32_t)r * 256u + (uint32_t)(((k >> 3) ^ (r & 7)) << 4)
         + (uint32_t)((k & 7) << 1);
}

// ------------------------------ CSR build ---------------------------------

__global__ void k_zero_int(int* p, int n) {
    int i = blockIdx.x * blockDim.x + threadIdx.x;
    if (i < n) p[i] = 0;
}

__global__ void k_count(const int* __restrict__ dst, int* __restrict__ cnt, int E) {
    int i = blockIdx.x * blockDim.x + threadIdx.x;
    if (i < E) atomicAdd(&cnt[dst[i]], 1);
}

__global__ void k_scan1(const int* __restrict__ cnt, int* __restrict__ row,
                        int* __restrict__ bsum, int N) {
    __shared__ int sh[1024];
    int tid = threadIdx.x;
    int idx = blockIdx.x * 1024 + tid;
    int c = (idx < N) ? cnt[idx] : 0;
    sh[tid] = c;
    __syncthreads();
    #pragma unroll
    for (int off = 1; off < 1024; off <<= 1) {
        int t = (tid >= off) ? sh[tid - off] : 0;
        __syncthreads();
        sh[tid] += t;
        __syncthreads();
    }
    if (idx < N) row[idx] = sh[tid] - c;
    if (tid == 1023) bsum[blockIdx.x] = sh[1023];
}

__global__ void k_scan2(int* __restrict__ bsum, int nb) {
    __shared__ int sh[64];
    int tid = threadIdx.x;
    int v = (tid < nb) ? bsum[tid] : 0;
    sh[tid] = v;
    __syncthreads();
    #pragma unroll
    for (int off = 1; off < 64; off <<= 1) {
        int t = (tid >= off) ? sh[tid - off] : 0;
        __syncthreads();
        sh[tid] += t;
        __syncthreads();
    }
    if (tid < nb) bsum[tid] = sh[tid] - v;
}

__global__ void k_scan3(int* __restrict__ row, const int* __restrict__ bsum,
                        int* __restrict__ cursor, int N, int E) {
    int idx = blockIdx.x * 1024 + threadIdx.x;
    if (idx < N) {
        int v = row[idx] + bsum[blockIdx.x];
        row[idx] = v;
        cursor[idx] = v;
    }
    if (idx == 0) row[N] = E;
}

__global__ void k_scatter(const int* __restrict__ src, const int* __restrict__ dst,
                          int* __restrict__ cursor, int* __restrict__ srcperm, int E) {
    int i = blockIdx.x * blockDim.x + threadIdx.x;
    if (i < E) {
        int d = dst[i];
        int pos = atomicAdd(&cursor[d], 1);
        srcperm[pos] = src[i];
    }
}

// --------------------------- W split/transpose ------------------------------
// W [128 k][C n] fp32 -> B tiles [C n][128 k] bf16 hi/lo, swizzled layout.

__global__ void k_wsplit(const float* __restrict__ W, int C,
                         uint16_t* __restrict__ hi, uint16_t* __restrict__ lo) {
    int idx = blockIdx.x * blockDim.x + threadIdx.x;
    if (idx >= 128 * C) return;
    int k = idx / C;           // 0..127
    int n = idx % C;
    float v = W[idx];
    __nv_bfloat16 h = __float2bfloat16_rn(v);
    float r = v - __bfloat162float(h);
    __nv_bfloat16 l = __float2bfloat16_rn(r);
    uint32_t off16 = tile_off(n, k) >> 1;  // uint16 units
    hi[off16] = *(uint16_t*)&h;
    lo[off16] = *(uint16_t*)&l;
}

// ------------------------------ MMA GEMM ------------------------------------
// out[N,C] = X[N,128] @ W[128,C]. CTA = 128 rows x C cols, 8 warps,
// warp tile 16 x C. 3-term bf16 split accumulated in fp32.

template <int C>
__global__ void __launch_bounds__(256, 1)
k_gemm_mma(const float* __restrict__ X,
           const uint16_t* __restrict__ whi, const uint16_t* __restrict__ wlo,
           float* __restrict__ out, int N) {
    extern __shared__ char sm[];
    constexpr int A_HI = 0;
    constexpr int A_LO = 32768;
    constexpr int B_HI = 65536;
    constexpr int BSZ  = C * 256;
    constexpr int B_LO = B_HI + BSZ;

    const int tid  = threadIdx.x;
    const int lane = tid & 31;
    const int wid  = tid >> 5;
    const int r0   = blockIdx.x * 128;
    const uint32_t sbase = smem_u32(sm);

    // copy pre-swizzled B (linear float4 copies)
    #pragma unroll
    for (int i = tid; i < BSZ / 16; i += 256) {
        ((float4*)(sm + B_HI))[i] = ((const float4*)whi)[i];
        ((float4*)(sm + B_LO))[i] = ((const float4*)wlo)[i];
    }

    // convert A tile: 128 rows x 128 k -> bf16 hi/lo, swizzled
    #pragma unroll
    for (int idx = tid; idx < 128 * 64; idx += 256) {
        int m = idx >> 6;
        int k2 = idx & 63;
        int row = r0 + m;
        float2 v = (row < N) ? ((const float2*)X)[(size_t)row * 64 + k2]
                             : make_float2(0.f, 0.f);
        uint32_t hw, lw;
        split2(v, hw, lw);
        uint32_t off = tile_off(m, k2 * 2);
        *(uint32_t*)(sm + A_HI + off) = hw;
        *(uint32_t*)(sm + A_LO + off) = lw;
    }
    __syncthreads();

    // per-warp fragment setup
    const int m0 = wid * 16;
    const int a_row = m0 + (lane & 15);
    const uint32_t a_base = sbase + A_HI + (uint32_t)a_row * 256u;
    const int b_rowoff = (lane & 7) + ((lane >> 4) << 3);
    const uint32_t b_base = sbase + B_HI + (uint32_t)b_rowoff * 256u;
    const int lxor = lane & 7;

    constexpr int NT = C / 16;
    float acc[2 * NT][4];
    #pragma unroll
    for (int i = 0; i < 2 * NT; ++i)
        #pragma unroll
        for (int j = 0; j < 4; ++j) acc[i][j] = 0.f;

    #pragma unroll
    for (int ks = 0; ks < 8; ++ks) {
        uint32_t pa = (uint32_t)(((2 * ks + (lane >> 4)) ^ lxor) << 4);
        uint32_t ah[4], al[4];
        LDSM4(ah, a_base + pa);
        LDSM4(al, a_base + pa + (A_LO - A_HI));

        uint32_t pb = (uint32_t)(((2 * ks + ((lane >> 3) & 1)) ^ lxor) << 4);
        #pragma unroll
        for (int nt = 0; nt < NT; ++nt) {
            uint32_t baddr = b_base + (uint32_t)nt * 4096u + pb;
            uint32_t bh[4], bl[4];
            LDSM4(bh, baddr);
            LDSM4(bl, baddr + (uint32_t)(B_LO - B_HI));
            MMA16816(acc[2 * nt],     ah, bh[0], bh[1]);
            MMA16816(acc[2 * nt],     al, bh[0], bh[1]);
            MMA16816(acc[2 * nt],     ah, bl[0], bl[1]);
            MMA16816(acc[2 * nt + 1], ah, bh[2], bh[3]);
            MMA16816(acc[2 * nt + 1], al, bh[2], bh[3]);
            MMA16816(acc[2 * nt + 1], ah, bl[2], bl[3]);
        }
    }

    // epilogue: lane holds (m = l/4 (+8), n = 2*(l%4) (+1)) per n8 tile
    const int er_ = r0 + m0 + (lane >> 2);
    const int ec = (lane & 3) * 2;
    #pragma unroll
    for (int t = 0; t < 2 * NT; ++t) {
        int col = t * 8 + ec;
        if (er_ < N)
            *(float2*)(out + (size_t)er_ * C + col) = make_float2(acc[t][0], acc[t][1]);
        if (er_ + 8 < N)
            *(float2*)(out + (size_t)(er_ + 8) * C + col) = make_float2(acc[t][2], acc[t][3]);
    }
}

// ------------------------------ EL / ER ------------------------------------

template <int C, int H>
__global__ void k_elr(const float* __restrict__ feat, const float* __restrict__ al,
                      const float* __restrict__ ar, float* __restrict__ el,
                      float* __restrict__ er, int N) {
    int warp = (blockIdx.x * blockDim.x + threadIdx.x) >> 5;
    int lane = threadIdx.x & 31;
    if (warp >= N) return;
    constexpr int V = C / 32;
    constexpr int D = C / H;
    constexpr int G = D / V;

    float pl = 0.f, pr = 0.f;
    #pragma unroll
    for (int v = 0; v < V; ++v) {
        float f = feat[(size_t)warp * C + lane * V + v];
        pl += f * al[lane * V + v];
        pr += f * ar[lane * V + v];
    }
    #pragma unroll
    for (int off = G / 2; off > 0; off >>= 1) {
        pl += __shfl_xor_sync(0xffffffffu, pl, off);
        pr += __shfl_xor_sync(0xffffffffu, pr, off);
    }
    if ((lane % G) == 0) {
        int h = lane / G;
        el[warp * H + h] = pl;
        er[warp * H + h] = pr;
    }
}

// ------------------------------ Aggregation --------------------------------

template <int C, int H, bool RELU>
__global__ void k_agg(const float* __restrict__ feat, const float* __restrict__ el,
                      const float* __restrict__ er, const int* __restrict__ rowp,
                      const int* __restrict__ srcperm, const float* __restrict__ bias,
                      float* __restrict__ out, int N) {
    int warp = (blockIdx.x * blockDim.x + threadIdx.x) >> 5;
    int lane = threadIdx.x & 31;
    if (warp >= N) return;
    constexpr int V = C / 32;
    constexpr int D = C / H;
    const int h0 = (lane * V) / D;

    float erv = er[warp * H + h0];
    float acc[V];
    #pragma unroll
    for (int v = 0; v < V; ++v) acc[v] = 0.f;
    float denom = 0.f;

    int s = rowp[warp];
    const int send = rowp[warp + 1];

    #pragma unroll 1
    for (; s + 8 <= send; s += 8) {
        int a[8];
        #pragma unroll
        for (int q = 0; q < 8; ++q) a[q] = srcperm[s + q];
        float w[8];
        #pragma unroll
        for (int q = 0; q < 8; ++q) {
            float e = el[a[q] * H + h0] + erv;
            e = (e > 0.f) ? e : 0.2f * e;
            w[q] = __expf(e);
            denom += w[q];
        }
        if constexpr (V == 4) {
            #pragma unroll
            for (int q = 0; q < 8; ++q) {
                float4 f = ((const float4*)(feat + (size_t)a[q] * C))[lane];
                acc[0] += f.x * w[q]; acc[1] += f.y * w[q];
                acc[2] += f.z * w[q]; acc[3] += f.w * w[q];
            }
        } else {
            #pragma unroll
            for (int q = 0; q < 8; ++q) {
                float2 f = ((const float2*)(feat + (size_t)a[q] * C))[lane];
                acc[0] += f.x * w[q]; acc[1] += f.y * w[q];
            }
        }
    }
    for (; s < send; ++s) {
        int sn = srcperm[s];
        float e = el[sn * H + h0] + erv;
        e = (e > 0.f) ? e : 0.2f * e;
        float w = __expf(e);
        denom += w;
        if constexpr (V == 4) {
            float4 f = ((const float4*)(feat + (size_t)sn * C))[lane];
            acc[0] += f.x * w; acc[1] += f.y * w;
            acc[2] += f.z * w; acc[3] += f.w * w;
        } else {
            float2 f = ((const float2*)(feat + (size_t)sn * C))[lane];
            acc[0] += f.x * w; acc[1] += f.y * w;
        }
    }

    float inv = 1.f / fmaxf(denom, 1e-12f);
    float res[V];
    #pragma unroll
    for (int v = 0; v < V; ++v) {
        float o = acc[v] * inv + bias[lane * V + v];
        if (RELU) o = fmaxf(o, 0.f);
        res[v] = o;
    }
    if constexpr (V == 4) {
        ((float4*)(out + (size_t)warp * C))[lane] =
            make_float4(res[0], res[1], res[2], res[3]);
    } else {
        ((float2*)(out + (size_t)warp * C))[lane] = make_float2(res[0], res[1]);
    }
}

// ------------------------------ Host ---------------------------------------

extern "C" void kernel_launch(void* const* d_in, const int* in_sizes, int n_in,
                              void* d_out, int out_size) {
    const float* features = (const float*)d_in[0];
    const int*   src      = (const int*)d_in[1];
    const int*   dst      = (const int*)d_in[2];
    const float* W0  = (const float*)d_in[3];
    const float* al0 = (const float*)d_in[4];
    const float* ar0 = (const float*)d_in[5];
    const float* b0  = (const float*)d_in[6];
    const float* W1  = (const float*)d_in[7];
    const float* al1 = (const float*)d_in[8];
    const float* ar1 = (const float*)d_in[9];
    const float* b1  = (const float*)d_in[10];
    const float* W2  = (const float*)d_in[11];
    const float* al2 = (const float*)d_in[12];
    const float* ar2 = (const float*)d_in[13];
    const float* b2  = (const float*)d_in[14];

    const int N = in_sizes[0] / 128;
    const int E = in_sizes[1];

    float *feat, *h, *el, *er;
    int *cnt, *row, *bsum, *srcperm;
    uint16_t *whi0, *wlo0, *whi1, *wlo1, *whi2, *wlo2;
    cudaGetSymbolAddress((void**)&feat, g_feat);
    cudaGetSymbolAddress((void**)&h, g_h);
    cudaGetSymbolAddress((void**)&el, g_el);
    cudaGetSymbolAddress((void**)&er, g_er);
    cudaGetSymbolAddress((void**)&cnt, g_cnt);
    cudaGetSymbolAddress((void**)&row, g_row);
    cudaGetSymbolAddress((void**)&bsum, g_bsum);
    cudaGetSymbolAddress((void**)&srcperm, g_srcperm);
    cudaGetSymbolAddress((void**)&whi0, g_whi0);
    cudaGetSymbolAddress((void**)&wlo0, g_wlo0);
    cudaGetSymbolAddress((void**)&whi1, g_whi1);
    cudaGetSymbolAddress((void**)&wlo1, g_wlo1);
    cudaGetSymbolAddress((void**)&whi2, g_whi2);
    cudaGetSymbolAddress((void**)&wlo2, g_wlo2);

    const int smem128 = 65536 + 2 * 128 * 256; // 131072
    const int smem64  = 65536 + 2 * 64 * 256;  //  98304
    cudaFuncSetAttribute(k_gemm_mma<128>, cudaFuncAttributeMaxDynamicSharedMemorySize, smem128);
    cudaFuncSetAttribute(k_gemm_mma<64>,  cudaFuncAttributeMaxDynamicSharedMemorySize, smem64);

    const int nb = (N + 1023) / 1024;
    const int gemm_blocks = (N + 127) / 128;
    const int node_warp_blocks = (N + 7) / 8;

    // W pre-split (launches 1-3); GEMM0 is launch #4 (ncu capture target)
    k_wsplit<<<(128 * 128 + 255) / 256, 256>>>(W0, 128, whi0, wlo0);
    k_wsplit<<<(128 * 128 + 255) / 256, 256>>>(W1, 128, whi1, wlo1);
    k_wsplit<<<(128 * 64 + 255) / 256, 256>>>(W2, 64, whi2, wlo2);

    k_gemm_mma<128><<<gemm_blocks, 256, smem128>>>(features, whi0, wlo0, feat, N);

    // CSR build (dst identical for all layers)
    k_zero_int<<<(N + 255) / 256, 256>>>(cnt, N);
    k_count<<<(E + 255) / 256, 256>>>(dst, cnt, E);
    k_scan1<<<nb, 1024>>>(cnt, row, bsum, N);
    k_scan2<<<1, 64>>>(bsum, nb);
    k_scan3<<<nb, 1024>>>(row, bsum, cnt, N, E);
    k_scatter<<<(E + 255) / 256, 256>>>(src, dst, cnt, srcperm, E);

    // Layer 0
    k_elr<128, 4><<<node_warp_blocks, 256>>>(feat, al0, ar0, el, er, N);
    k_agg<128, 4, true><<<node_warp_blocks, 256>>>(feat, el, er, row, srcperm, b0, h, N);

    // Layer 1
    k_gemm_mma<128><<<gemm_blocks, 256, smem128>>>(h, whi1, wlo1, feat, N);
    k_elr<128, 4><<<node_warp_blocks, 256>>>(feat, al1, ar1, el, er, N);
    k_agg<128, 4, true><<<node_warp_blocks, 256>>>(feat, el, er, row, srcperm, b1, h, N);

    // Layer 2
    k_gemm_mma<64><<<gemm_blocks, 256, smem64>>>(h, whi2, wlo2, feat, N);
    k_elr<64, 1><<<node_warp_blocks, 256>>>(feat, al2, ar2, el, er, N);
    k_agg<64, 1, false><<<node_warp_blocks, 256>>>(feat, el, er, row, srcperm, b2,
                                                   (float*)d_out, N);
}

// round 6
// speedup vs baseline: 1.3624x; 1.0566x over previous
#include <cuda_runtime.h>
#include <cuda_bf16.h>
#include <cuda_fp16.h>
#include <cstdint>

// ---------------------------------------------------------------------------
// GAT, 3 layers.
//   GEMM: mma.sync m16n8k16 bf16 (fp32 acc), 3-term bf16 split of fp32 inputs.
//         512 threads, 16 warps (8M x 2N), K-chunked A staging, cp.async B.
//         Epilogue stores feat as fp16 (consumed only by ELR/AGG).
//   AGG:  warp-per-node softmax aggregation over dst-CSR, fp16 messages,
//         fp32 accumulation, 8-edge batching. Max-shift dropped (exact).
// ---------------------------------------------------------------------------

#define NNODES_MAX 50000
#define NEDGES_MAX 800000

__device__ __align__(16) __half g_feath[NNODES_MAX * 128];
__device__ float g_h   [NNODES_MAX * 128];
__device__ float g_el  [NNODES_MAX * 4];
__device__ float g_er  [NNODES_MAX * 4];
__device__ int   g_cnt [NNODES_MAX];
__device__ int   g_row [NNODES_MAX + 1];
__device__ int   g_bsum[64];
__device__ int   g_srcperm[NEDGES_MAX];

// Pre-split, pre-swizzled W operands: [C n][128 k] bf16, row stride 256 B.
__device__ __align__(16) uint16_t g_whi0[128 * 128], g_wlo0[128 * 128];
__device__ __align__(16) uint16_t g_whi1[128 * 128], g_wlo1[128 * 128];
__device__ __align__(16) uint16_t g_whi2[64 * 128],  g_wlo2[64 * 128];

// ------------------------------ PTX helpers --------------------------------

#define LDSM4(r, addr)                                                        \
    asm volatile("ldmatrix.sync.aligned.m8n8.x4.shared.b16 {%0,%1,%2,%3}, [%4];" \
        : "=r"((r)[0]), "=r"((r)[1]), "=r"((r)[2]), "=r"((r)[3]) : "r"(addr))

#define MMA16816(d, a, b0, b1)                                                \
    asm volatile("mma.sync.aligned.m16n8k16.row.col.f32.bf16.bf16.f32 "       \
        "{%0,%1,%2,%3}, {%4,%5,%6,%7}, {%8,%9}, {%0,%1,%2,%3};"               \
        : "+f"((d)[0]), "+f"((d)[1]), "+f"((d)[2]), "+f"((d)[3])              \
        : "r"((a)[0]), "r"((a)[1]), "r"((a)[2]), "r"((a)[3]), "r"(b0), "r"(b1))

#define CP_ASYNC16(dst, src)                                                  \
    asm volatile("cp.async.cg.shared.global [%0], [%1], 16;"                  \
        :: "r"(dst), "l"(src))
#define CP_COMMIT() asm volatile("cp.async.commit_group;" ::: "memory")
#define CP_WAIT0()  asm volatile("cp.async.wait_group 0;" ::: "memory")

__device__ __forceinline__ uint32_t smem_u32(const void* p) {
    uint32_t a;
    asm("{ .reg .u64 t; cvta.to.shared.u64 t, %1; cvt.u32.u64 %0, t; }"
        : "=r"(a) : "l"(p));
    return a;
}

__device__ __forceinline__ void split2(float2 v, uint32_t& hi, uint32_t& lo) {
    __nv_bfloat162 h2 = __float22bfloat162_rn(v);
    float rx = v.x - __bfloat162float(h2.x);
    float ry = v.y - __bfloat162float(h2.y);
    __nv_bfloat162 l2 = __float22bfloat162_rn(make_float2(rx, ry));
    hi = *(uint32_t*)&h2;
    lo = *(uint32_t*)&l2;
}

// B tile: [C rows][128 k], row stride 256 B, 16B-chunk XOR swizzle
__device__ __forceinline__ uint32_t tile_offB(int r, int k) {
    return (uint32_t)r * 256u + (uint32_t)(((k >> 3) ^ (r & 7)) << 4)
         + (uint32_t)((k & 7) << 1);
}
// A chunk tile: [128 rows][64 k], row stride 128 B, same chunk swizzle
__device__ __forceinline__ uint32_t tile_offA(int r, int k) {
    return (uint32_t)r * 128u + (uint32_t)(((k >> 3) ^ (r & 7)) << 4)
         + (uint32_t)((k & 7) << 1);
}

// ------------------------------ CSR build ---------------------------------

__global__ void k_zero_int(int* p, int n) {
    int i = blockIdx.x * blockDim.x + threadIdx.x;
    if (i < n) p[i] = 0;
}

__global__ void k_count(const int* __restrict__ dst, int* __restrict__ cnt, int E) {
    int i = blockIdx.x * blockDim.x + threadIdx.x;
    if (i < E) atomicAdd(&cnt[dst[i]], 1);
}

__global__ void k_scan1(const int* __restrict__ cnt, int* __restrict__ row,
                        int* __restrict__ bsum, int N) {
    __shared__ int sh[1024];
    int tid = threadIdx.x;
    int idx = blockIdx.x * 1024 + tid;
    int c = (idx < N) ? cnt[idx] : 0;
    sh[tid] = c;
    __syncthreads();
    #pragma unroll
    for (int off = 1; off < 1024; off <<= 1) {
        int t = (tid >= off) ? sh[tid - off] : 0;
        __syncthreads();
        sh[tid] += t;
        __syncthreads();
    }
    if (idx < N) row[idx] = sh[tid] - c;
    if (tid == 1023) bsum[blockIdx.x] = sh[1023];
}

__global__ void k_scan2(int* __restrict__ bsum, int nb) {
    __shared__ int sh[64];
    int tid = threadIdx.x;
    int v = (tid < nb) ? bsum[tid] : 0;
    sh[tid] = v;
    __syncthreads();
    #pragma unroll
    for (int off = 1; off < 64; off <<= 1) {
        int t = (tid >= off) ? sh[tid - off] : 0;
        __syncthreads();
        sh[tid] += t;
        __syncthreads();
    }
    if (tid < nb) bsum[tid] = sh[tid] - v;
}

__global__ void k_scan3(int* __restrict__ row, const int* __restrict__ bsum,
                        int* __restrict__ cursor, int N, int E) {
    int idx = blockIdx.x * 1024 + threadIdx.x;
    if (idx < N) {
        int v = row[idx] + bsum[blockIdx.x];
        row[idx] = v;
        cursor[idx] = v;
    }
    if (idx == 0) row[N] = E;
}

__global__ void k_scatter(const int* __restrict__ src, const int* __restrict__ dst,
                          int* __restrict__ cursor, int* __restrict__ srcperm, int E) {
    int i = blockIdx.x * blockDim.x + threadIdx.x;
    if (i < E) {
        int d = dst[i];
        int pos = atomicAdd(&cursor[d], 1);
        srcperm[pos] = src[i];
    }
}

// --------------------------- W split/transpose ------------------------------

__global__ void k_wsplit(const float* __restrict__ W, int C,
                         uint16_t* __restrict__ hi, uint16_t* __restrict__ lo) {
    int idx = blockIdx.x * blockDim.x + threadIdx.x;
    if (idx >= 128 * C) return;
    int k = idx / C;
    int n = idx % C;
    float v = W[idx];
    __nv_bfloat16 h = __float2bfloat16_rn(v);
    float r = v - __bfloat162float(h);
    __nv_bfloat16 l = __float2bfloat16_rn(r);
    uint32_t off16 = tile_offB(n, k) >> 1;
    hi[off16] = *(uint16_t*)&h;
    lo[off16] = *(uint16_t*)&l;
}

// ------------------------------ MMA GEMM ------------------------------------
// out_h[N,C](fp16) = X[N,128](fp32) @ W[128,C]. CTA = 128 rows, 512 threads,
// 16 warps (8M x 2N), warp tile 16 x C/2. K staged in 2 chunks of 64.

template <int C>
__global__ void __launch_bounds__(512, 1)
k_gemm_mma(const float* __restrict__ X,
           const uint16_t* __restrict__ whi, const uint16_t* __restrict__ wlo,
           __half* __restrict__ outh, int N) {
    extern __shared__ char sm[];
    constexpr int A_HI = 0;           // 128 rows x 128 B = 16 KB
    constexpr int A_LO = 16384;
    constexpr int B_HI = 32768;
    constexpr int BSZ  = C * 256;
    constexpr int B_LO = B_HI + BSZ;

    const int tid  = threadIdx.x;
    const int lane = tid & 31;
    const int wid  = tid >> 5;
    const int r0   = blockIdx.x * 128;
    const uint32_t sbase = smem_u32(sm);

    // async copy of pre-swizzled B (hi+lo)
    #pragma unroll
    for (int i = tid; i < BSZ / 16; i += 512) {
        CP_ASYNC16(sbase + B_HI + i * 16, (const char*)whi + i * 16);
        CP_ASYNC16(sbase + B_LO + i * 16, (const char*)wlo + i * 16);
    }
    CP_COMMIT();

    // warp mapping: 8 M-warps x 2 N-halves
    const int m0 = (wid & 7) * 16;
    const int n0 = (wid >> 3) * (C / 2);
    constexpr int NT = C / 32;         // n16 tiles per warp
    const int a_row = m0 + (lane & 15);
    const uint32_t a_base = sbase + A_HI + (uint32_t)a_row * 128u;
    const int lxor = lane & 7;
    const uint32_t b_base = sbase + B_HI
        + (uint32_t)(n0 + (lane & 7) + ((lane >> 4) << 3)) * 256u;

    float acc[2 * NT][4];
    #pragma unroll
    for (int i = 0; i < 2 * NT; ++i)
        #pragma unroll
        for (int j = 0; j < 4; ++j) acc[i][j] = 0.f;

    #pragma unroll
    for (int kc = 0; kc < 2; ++kc) {
        // stage A chunk: 128 rows x 64 k -> bf16 hi/lo, swizzled
        #pragma unroll
        for (int idx = tid; idx < 128 * 32; idx += 512) {
            int m = idx >> 5;
            int k2 = idx & 31;
            int row = r0 + m;
            float2 v = (row < N)
                ? ((const float2*)X)[(size_t)row * 64 + kc * 32 + k2]
                : make_float2(0.f, 0.f);
            uint32_t hw, lw;
            split2(v, hw, lw);
            uint32_t off = tile_offA(m, k2 * 2);
            *(uint32_t*)(sm + A_HI + off) = hw;
            *(uint32_t*)(sm + A_LO + off) = lw;
        }
        if (kc == 0) CP_WAIT0();
        __syncthreads();

        #pragma unroll
        for (int ks = 0; ks < 4; ++ks) {
            uint32_t pa = (uint32_t)(((2 * ks + (lane >> 4)) ^ lxor) << 4);
            uint32_t ah[4], al[4];
            LDSM4(ah, a_base + pa);
            LDSM4(al, a_base + pa + 16384u);

            int kks = kc * 4 + ks;
            uint32_t pb = (uint32_t)(((2 * kks + ((lane >> 3) & 1)) ^ lxor) << 4);
            #pragma unroll
            for (int nt = 0; nt < NT; ++nt) {
                uint32_t baddr = b_base + (uint32_t)nt * 4096u + pb;
                uint32_t bh[4], bl[4];
                LDSM4(bh, baddr);
                LDSM4(bl, baddr + (uint32_t)BSZ);
                MMA16816(acc[2 * nt],     ah, bh[0], bh[1]);
                MMA16816(acc[2 * nt],     al, bh[0], bh[1]);
                MMA16816(acc[2 * nt],     ah, bl[0], bl[1]);
                MMA16816(acc[2 * nt + 1], ah, bh[2], bh[3]);
                MMA16816(acc[2 * nt + 1], al, bh[2], bh[3]);
                MMA16816(acc[2 * nt + 1], ah, bl[2], bl[3]);
            }
        }
        __syncthreads();
    }

    // epilogue -> fp16
    const int er_ = r0 + m0 + (lane >> 2);
    const int ec = (lane & 3) * 2;
    #pragma unroll
    for (int t = 0; t < 2 * NT; ++t) {
        int col = n0 + t * 8 + ec;
        if (er_ < N)
            *(__half2*)(outh + (size_t)er_ * C + col) =
                __floats2half2_rn(acc[t][0], acc[t][1]);
        if (er_ + 8 < N)
            *(__half2*)(outh + (size_t)(er_ + 8) * C + col) =
                __floats2half2_rn(acc[t][2], acc[t][3]);
    }
}

// ------------------------------ EL / ER ------------------------------------

template <int C, int H>
__global__ void k_elr(const __half* __restrict__ feat, const float* __restrict__ al,
                      const float* __restrict__ ar, float* __restrict__ el,
                      float* __restrict__ er, int N) {
    int warp = (blockIdx.x * blockDim.x + threadIdx.x) >> 5;
    int lane = threadIdx.x & 31;
    if (warp >= N) return;
    constexpr int V = C / 32;
    constexpr int D = C / H;
    constexpr int G = D / V;

    float f[V];
    if constexpr (V == 4) {
        uint2 u = ((const uint2*)(feat + (size_t)warp * C))[lane];
        float2 f01 = __half22float2(*(__half2*)&u.x);
        float2 f23 = __half22float2(*(__half2*)&u.y);
        f[0] = f01.x; f[1] = f01.y; f[2] = f23.x; f[3] = f23.y;
    } else {
        float2 f01 = __half22float2(((const __half2*)(feat + (size_t)warp * C))[lane]);
        f[0] = f01.x; f[1] = f01.y;
    }

    float pl = 0.f, pr = 0.f;
    #pragma unroll
    for (int v = 0; v < V; ++v) {
        pl += f[v] * al[lane * V + v];
        pr += f[v] * ar[lane * V + v];
    }
    #pragma unroll
    for (int off = G / 2; off > 0; off >>= 1) {
        pl += __shfl_xor_sync(0xffffffffu, pl, off);
        pr += __shfl_xor_sync(0xffffffffu, pr, off);
    }
    if ((lane % G) == 0) {
        int h = lane / G;
        el[warp * H + h] = pl;
        er[warp * H + h] = pr;
    }
}

// ------------------------------ Aggregation --------------------------------
// Warp per destination node; fp16 messages, fp32 accumulation; 8-edge batch.

template <int C, int H, bool RELU>
__global__ void k_agg(const __half* __restrict__ feat, const float* __restrict__ el,
                      const float* __restrict__ er, const int* __restrict__ rowp,
                      const int* __restrict__ srcperm, const float* __restrict__ bias,
                      float* __restrict__ out, int N) {
    int warp = (blockIdx.x * blockDim.x + threadIdx.x) >> 5;
    int lane = threadIdx.x & 31;
    if (warp >= N) return;
    constexpr int V = C / 32;
    constexpr int D = C / H;
    const int h0 = (lane * V) / D;

    float erv = er[warp * H + h0];
    float acc[V];
    #pragma unroll
    for (int v = 0; v < V; ++v) acc[v] = 0.f;
    float denom = 0.f;

    int s = rowp[warp];
    const int send = rowp[warp + 1];

    #pragma unroll 1
    for (; s + 8 <= send; s += 8) {
        int a[8];
        #pragma unroll
        for (int q = 0; q < 8; ++q) a[q] = srcperm[s + q];
        float w[8];
        #pragma unroll
        for (int q = 0; q < 8; ++q) {
            float e = el[a[q] * H + h0] + erv;
            e = (e > 0.f) ? e : 0.2f * e;
            w[q] = __expf(e);
            denom += w[q];
        }
        if constexpr (V == 4) {
            uint2 u[8];
            #pragma unroll
            for (int q = 0; q < 8; ++q)
                u[q] = ((const uint2*)(feat + (size_t)a[q] * C))[lane];
            #pragma unroll
            for (int q = 0; q < 8; ++q) {
                float2 f01 = __half22float2(*(__half2*)&u[q].x);
                float2 f23 = __half22float2(*(__half2*)&u[q].y);
                acc[0] += f01.x * w[q]; acc[1] += f01.y * w[q];
                acc[2] += f23.x * w[q]; acc[3] += f23.y * w[q];
            }
        } else {
            __half2 u[8];
            #pragma unroll
            for (int q = 0; q < 8; ++q)
                u[q] = ((const __half2*)(feat + (size_t)a[q] * C))[lane];
            #pragma unroll
            for (int q = 0; q < 8; ++q) {
                float2 f01 = __half22float2(u[q]);
                acc[0] += f01.x * w[q]; acc[1] += f01.y * w[q];
            }
        }
    }
    for (; s < send; ++s) {
        int sn = srcperm[s];
        float e = el[sn * H + h0] + erv;
        e = (e > 0.f) ? e : 0.2f * e;
        float w = __expf(e);
        denom += w;
        if constexpr (V == 4) {
            uint2 u = ((const uint2*)(feat + (size_t)sn * C))[lane];
            float2 f01 = __half22float2(*(__half2*)&u.x);
            float2 f23 = __half22float2(*(__half2*)&u.y);
            acc[0] += f01.x * w; acc[1] += f01.y * w;
            acc[2] += f23.x * w; acc[3] += f23.y * w;
        } else {
            float2 f01 = __half22float2(((const __half2*)(feat + (size_t)sn * C))[lane]);
            acc[0] += f01.x * w; acc[1] += f01.y * w;
        }
    }

    float inv = 1.f / fmaxf(denom, 1e-12f);
    float res[V];
    #pragma unroll
    for (int v = 0; v < V; ++v) {
        float o = acc[v] * inv + bias[lane * V + v];
        if (RELU) o = fmaxf(o, 0.f);
        res[v] = o;
    }
    if constexpr (V == 4) {
        ((float4*)(out + (size_t)warp * C))[lane] =
            make_float4(res[0], res[1], res[2], res[3]);
    } else {
        ((float2*)(out + (size_t)warp * C))[lane] = make_float2(res[0], res[1]);
    }
}

// ------------------------------ Host ---------------------------------------

extern "C" void kernel_launch(void* const* d_in, const int* in_sizes, int n_in,
                              void* d_out, int out_size) {
    const float* features = (const float*)d_in[0];
    const int*   src      = (const int*)d_in[1];
    const int*   dst      = (const int*)d_in[2];
    const float* W0  = (const float*)d_in[3];
    const float* al0 = (const float*)d_in[4];
    const float* ar0 = (const float*)d_in[5];
    const float* b0  = (const float*)d_in[6];
    const float* W1  = (const float*)d_in[7];
    const float* al1 = (const float*)d_in[8];
    const float* ar1 = (const float*)d_in[9];
    const float* b1  = (const float*)d_in[10];
    const float* W2  = (const float*)d_in[11];
    const float* al2 = (const float*)d_in[12];
    const float* ar2 = (const float*)d_in[13];
    const float* b2  = (const float*)d_in[14];

    const int N = in_sizes[0] / 128;
    const int E = in_sizes[1];

    __half* feath;
    float *h, *el, *er;
    int *cnt, *row, *bsum, *srcperm;
    uint16_t *whi0, *wlo0, *whi1, *wlo1, *whi2, *wlo2;
    cudaGetSymbolAddress((void**)&feath, g_feath);
    cudaGetSymbolAddress((void**)&h, g_h);
    cudaGetSymbolAddress((void**)&el, g_el);
    cudaGetSymbolAddress((void**)&er, g_er);
    cudaGetSymbolAddress((void**)&cnt, g_cnt);
    cudaGetSymbolAddress((void**)&row, g_row);
    cudaGetSymbolAddress((void**)&bsum, g_bsum);
    cudaGetSymbolAddress((void**)&srcperm, g_srcperm);
    cudaGetSymbolAddress((void**)&whi0, g_whi0);
    cudaGetSymbolAddress((void**)&wlo0, g_wlo0);
    cudaGetSymbolAddress((void**)&whi1, g_whi1);
    cudaGetSymbolAddress((void**)&wlo1, g_wlo1);
    cudaGetSymbolAddress((void**)&whi2, g_whi2);
    cudaGetSymbolAddress((void**)&wlo2, g_wlo2);

    const int smem128 = 32768 + 2 * 128 * 256; // 98304
    const int smem64  = 32768 + 2 * 64 * 256;  // 65536
    cudaFuncSetAttribute(k_gemm_mma<128>, cudaFuncAttributeMaxDynamicSharedMemorySize, smem128);
    cudaFuncSetAttribute(k_gemm_mma<64>,  cudaFuncAttributeMaxDynamicSharedMemorySize, smem64);

    const int nb = (N + 1023) / 1024;
    const int gemm_blocks = (N + 127) / 128;
    const int node_warp_blocks = (N + 7) / 8;

    // W pre-split (launches 1-3); GEMM0 is launch #4 (ncu capture target)
    k_wsplit<<<(128 * 128 + 255) / 256, 256>>>(W0, 128, whi0, wlo0);
    k_wsplit<<<(128 * 128 + 255) / 256, 256>>>(W1, 128, whi1, wlo1);
    k_wsplit<<<(128 * 64 + 255) / 256, 256>>>(W2, 64, whi2, wlo2);

    k_gemm_mma<128><<<gemm_blocks, 512, smem128>>>(features, whi0, wlo0, feath, N);

    // CSR build (dst identical for all layers)
    k_zero_int<<<(N + 255) / 256, 256>>>(cnt, N);
    k_count<<<(E + 255) / 256, 256>>>(dst, cnt, E);
    k_scan1<<<nb, 1024>>>(cnt, row, bsum, N);
    k_scan2<<<1, 64>>>(bsum, nb);
    k_scan3<<<nb, 1024>>>(row, bsum, cnt, N, E);
    k_scatter<<<(E + 255) / 256, 256>>>(src, dst, cnt, srcperm, E);

    // Layer 0
    k_elr<128, 4><<<node_warp_blocks, 256>>>(feath, al0, ar0, el, er, N);
    k_agg<128, 4, true><<<node_warp_blocks, 256>>>(feath, el, er, row, srcperm, b0, h, N);

    // Layer 1
    k_gemm_mma<128><<<gemm_blocks, 512, smem128>>>(h, whi1, wlo1, feath, N);
    k_elr<128, 4><<<node_warp_blocks, 256>>>(feath, al1, ar1, el, er, N);
    k_agg<128, 4, true><<<node_warp_blocks, 256>>>(feath, el, er, row, srcperm, b1, h, N);

    // Layer 2
    k_gemm_mma<64><<<gemm_blocks, 512, smem64>>>(h, whi2, wlo2, feath, N);
    k_elr<64, 1><<<node_warp_blocks, 256>>>(feath, al2, ar2, el, er, N);
    k_agg<64, 1, false><<<node_warp_blocks, 256>>>(feath, el, er, row, srcperm, b2,
                                                   (float*)d_out, N);
}